// round 1
// baseline (speedup 1.0000x reference)
#include <cuda_runtime.h>

#define NMAX   100000
#define EMAX   3200000
#define FDIM   512
#define HID    32
#define C3     96          // 3 views * 32

// ---------------- device scratch (static: no allocation allowed) ----------------
__device__ int    g_is64;
__device__ float  g_dinv[3][NMAX];        // deg accumulator, then dinv in-place
__device__ int    g_cnt[NMAX];
__device__ int    g_off[NMAX + 1];
__device__ int    g_cursor[NMAX];
__device__ int    g_bsum[1024];
__device__ float4 g_csr[EMAX];            // {src_as_float_bits, norm0, norm1, norm2}
__device__ float  g_Wcat[FDIM * C3];
__device__ float  g_H[(size_t)NMAX * C3];
__device__ float  g_AGG[(size_t)NMAX * C3];
__device__ float  g_Z[(size_t)NMAX * C3];

// ---------------- dtype sniff: int64 edge_index has all-zero high words ----------
__global__ void k_detect(const unsigned int* __restrict__ wbuf, long long nwords) {
    __shared__ int s;
    if (threadIdx.x == 0) s = 1;
    __syncthreads();
    int ok = 1;
    for (long long i = threadIdx.x; i < 2048; i += blockDim.x) {
        long long wi = 2 * i + 1;
        if (wi < nwords && wbuf[wi] != 0u) ok = 0;
    }
    if (!ok) atomicAnd(&s, 0);
    __syncthreads();
    if (threadIdx.x == 0) g_is64 = s;
}

__device__ __forceinline__ int2 read_edge(const void* ei, int E, int e, int is64) {
    if (is64) {
        const long long* p = (const long long*)ei;
        return make_int2((int)p[e], (int)p[E + e]);
    } else {
        const int* p = (const int*)ei;
        return make_int2(p[e], p[E + e]);
    }
}

__global__ void k_init(int N) {
    int i = blockIdx.x * blockDim.x + threadIdx.x;
    if (i < N) {
        g_dinv[0][i] = 1.0f;   // self-loop weight 1 in degree
        g_dinv[1][i] = 1.0f;
        g_dinv[2][i] = 1.0f;
        g_cnt[i] = 0;
    }
}

__global__ void k_deg(const void* ei, const float* __restrict__ w,
                      const float* __restrict__ m1, const float* __restrict__ m2, int E) {
    int e = blockIdx.x * blockDim.x + threadIdx.x;
    if (e >= E) return;
    int is64 = g_is64;
    int2 sd = read_edge(ei, E, e, is64);
    float we = w[e];
    atomicAdd(&g_dinv[0][sd.y], we);
    atomicAdd(&g_dinv[1][sd.y], we * m1[e]);
    atomicAdd(&g_dinv[2][sd.y], we * m2[e]);
    atomicAdd(&g_cnt[sd.y], 1);
}

__global__ void k_rsqrt(int N) {
    int i = blockIdx.x * blockDim.x + threadIdx.x;
    if (i < 3 * N) {
        int v = i / N, n = i - v * N;
        g_dinv[v][n] = rsqrtf(g_dinv[v][n]);
    }
}

// ---------------- exclusive prefix sum of g_cnt -> g_off ----------------
__global__ void k_scan1(int N) {
    __shared__ int warpsum[16];
    int b = blockIdx.x, t = threadIdx.x;
    int i = b * 512 + t;
    int v = (i < N) ? g_cnt[i] : 0;
    int lane = t & 31, wid = t >> 5;
    int x = v;
    #pragma unroll
    for (int o = 1; o < 32; o <<= 1) {
        int y = __shfl_up_sync(0xFFFFFFFFu, x, o);
        if (lane >= o) x += y;
    }
    if (lane == 31) warpsum[wid] = x;
    __syncthreads();
    if (wid == 0) {
        int ws = (lane < 16) ? warpsum[lane] : 0;
        #pragma unroll
        for (int o = 1; o < 16; o <<= 1) {
            int y = __shfl_up_sync(0xFFFFFFFFu, ws, o);
            if (lane >= o) ws += y;
        }
        if (lane < 16) warpsum[lane] = ws;
    }
    __syncthreads();
    int base = (wid > 0) ? warpsum[wid - 1] : 0;
    if (i < N) g_off[i] = base + x - v;       // exclusive within block
    if (t == 511) g_bsum[b] = base + x;       // block total
}

__global__ void k_scan2(int NB) {
    __shared__ int sh[1024];
    int t = threadIdx.x;
    sh[t] = (t < NB) ? g_bsum[t] : 0;
    __syncthreads();
    for (int o = 1; o < 1024; o <<= 1) {
        int v = sh[t];
        int add = (t >= o) ? sh[t - o] : 0;
        __syncthreads();
        sh[t] = v + add;
        __syncthreads();
    }
    if (t < NB) g_bsum[t] = (t > 0) ? sh[t - 1] : 0;   // exclusive
}

__global__ void k_scan3(int N, int E) {
    int i = blockIdx.x * blockDim.x + threadIdx.x;
    if (i < N) {
        int o = g_off[i] + g_bsum[i >> 9];
        g_off[i] = o;
        g_cursor[i] = o;
    }
    if (i == 0) g_off[N] = E;
}

// ---------------- scatter edges into CSR with precomputed per-view norms --------
__global__ void k_scatter(const void* ei, const float* __restrict__ w,
                          const float* __restrict__ m1, const float* __restrict__ m2, int E) {
    int e = blockIdx.x * blockDim.x + threadIdx.x;
    if (e >= E) return;
    int2 sd = read_edge(ei, E, e, g_is64);
    float we = w[e];
    float n0 = g_dinv[0][sd.x] * we * g_dinv[0][sd.y];
    float n1 = g_dinv[1][sd.x] * (we * m1[e]) * g_dinv[1][sd.y];
    float n2 = g_dinv[2][sd.x] * (we * m2[e]) * g_dinv[2][sd.y];
    int p = atomicAdd(&g_cursor[sd.y], 1);
    g_csr[p] = make_float4(__int_as_float(sd.x), n0, n1, n2);
}

// ---------------- fold feature masks into W1: Wcat[512, 96] ----------------
__global__ void k_wcat(const float* __restrict__ W1,
                       const float* __restrict__ fm1, const float* __restrict__ fm2) {
    int i = blockIdx.x * blockDim.x + threadIdx.x;
    if (i >= FDIM * C3) return;
    int k = i / C3, j = i - k * C3;
    int v = j >> 5, c = j & 31;
    float m = (v == 0) ? 1.0f : (v == 1 ? fm1[k] : fm2[k]);
    g_Wcat[i] = W1[k * HID + c] * m;
}

// ---------------- SGEMM: H[N,96] = x[N,512] @ Wcat[512,96] ----------------
// 128x96 block tile, BK=32, 256 threads, 8x6 micro-tile per thread.
__global__ __launch_bounds__(256) void k_gemm(const float* __restrict__ x, int N) {
    __shared__ float As[32][129];   // [k][m], pad 129 -> conflict-free
    __shared__ float Bs[32][100];   // [k][c]
    int tid = threadIdx.x;
    int ty = tid >> 4, tx = tid & 15;       // 16x16
    int row0 = blockIdx.x * 128;
    float acc[8][6];
    #pragma unroll
    for (int i = 0; i < 8; i++)
        #pragma unroll
        for (int j = 0; j < 6; j++) acc[i][j] = 0.0f;

    for (int k0 = 0; k0 < FDIM; k0 += 32) {
        #pragma unroll
        for (int l = 0; l < 16; l++) {        // 128*32 A elems
            int idx = tid + l * 256;
            int m = idx >> 5, k = idx & 31;
            int r = row0 + m;
            As[k][m] = (r < N) ? x[(size_t)r * FDIM + k0 + k] : 0.0f;
        }
        #pragma unroll
        for (int l = 0; l < 12; l++) {        // 32*96 B elems
            int idx = tid + l * 256;
            int k = idx / 96, c = idx - k * 96;
            Bs[k][c] = g_Wcat[(k0 + k) * C3 + c];
        }
        __syncthreads();
        #pragma unroll
        for (int kk = 0; kk < 32; kk++) {
            float a[8], b[6];
            #pragma unroll
            for (int i = 0; i < 8; i++) a[i] = As[kk][ty * 8 + i];
            #pragma unroll
            for (int j = 0; j < 6; j++) b[j] = Bs[kk][tx * 6 + j];
            #pragma unroll
            for (int i = 0; i < 8; i++)
                #pragma unroll
                for (int j = 0; j < 6; j++) acc[i][j] += a[i] * b[j];
        }
        __syncthreads();
    }
    #pragma unroll
    for (int i = 0; i < 8; i++) {
        int r = row0 + ty * 8 + i;
        if (r < N) {
            #pragma unroll
            for (int j = 0; j < 6; j++)
                g_H[(size_t)r * C3 + tx * 6 + j] = acc[i][j];
        }
    }
}

// ---------------- aggregation: warp per node, all 3 views at once ----------------
// AGG[n][v*32+c] = sum_{e: dst=n} H[src][v*32+c] * norm_v(e)
__global__ void k_agg(int N) {
    int warp = (blockIdx.x * blockDim.x + threadIdx.x) >> 5;
    int lane = threadIdx.x & 31;
    if (warp >= N) return;
    int beg = g_off[warp], end = g_off[warp + 1];
    float a0 = 0.f, a1 = 0.f, a2 = 0.f;
    for (int p = beg; p < end; p++) {
        float4 md = g_csr[p];
        int s = __float_as_int(md.x);
        const float* hr = &g_H[(size_t)s * C3];
        a0 += hr[lane]      * md.y;
        a1 += hr[lane + 32] * md.z;
        a2 += hr[lane + 64] * md.w;
    }
    size_t o = (size_t)warp * C3;
    g_AGG[o + lane]      = a0;
    g_AGG[o + lane + 32] = a1;
    g_AGG[o + lane + 64] = a2;
}

// ---------------- layer-1 epilogue: Z = relu(AGG + H*dinv^2 + b1) ----------------
__global__ void k_post1(const float* __restrict__ b1, int N) {
    size_t i = (size_t)blockIdx.x * blockDim.x + threadIdx.x;
    if (i >= (size_t)N * C3) return;
    int j = (int)(i % C3);
    int n = (int)(i / C3);
    int v = j >> 5, c = j & 31;
    float d = g_dinv[v][n];
    float val = g_AGG[i] + g_H[i] * d * d + b1[c];
    g_Z[i] = fmaxf(val, 0.0f);
}

// ---------------- layer-2 small GEMM: H = Z @ blockdiag(W2,W2,W2) ----------------
__global__ void k_h2(const float* __restrict__ W2, int N) {
    __shared__ float Ws[HID * HID];
    int t = threadIdx.x;
    for (int l = t; l < HID * HID; l += blockDim.x) Ws[l] = W2[l];
    __syncthreads();
    size_t i = (size_t)blockIdx.x * blockDim.x + t;
    if (i >= (size_t)N * C3) return;
    int j = (int)(i % C3);
    int n = (int)(i / C3);
    int v = j >> 5, c = j & 31;
    const float* zr = &g_Z[(size_t)n * C3 + v * 32];
    float acc = 0.0f;
    #pragma unroll
    for (int k = 0; k < HID; k++) acc += zr[k] * Ws[k * HID + c];
    g_H[i] = acc;
}

// ---------------- layer-2 epilogue + layout permute into d_out ----------------
// out[v][n][c] = relu(AGG[n][v*32+c] + H[n][v*32+c]*dinv_v[n]^2 + b2[c])
__global__ void k_post2(const float* __restrict__ b2, float* __restrict__ out, int N) {
    size_t i = (size_t)blockIdx.x * blockDim.x + threadIdx.x;
    if (i >= (size_t)N * C3) return;
    int j = (int)(i % C3);
    int n = (int)(i / C3);
    int v = j >> 5, c = j & 31;
    float d = g_dinv[v][n];
    float val = g_AGG[i] + g_H[i] * d * d + b2[c];
    out[((size_t)v * N + n) * HID + c] = fmaxf(val, 0.0f);
}

// =====================================================================
extern "C" void kernel_launch(void* const* d_in, const int* in_sizes, int n_in,
                              void* d_out, int out_size) {
    const float* x   = (const float*)d_in[0];
    const void*  ei  = d_in[1];
    const float* w   = (const float*)d_in[2];
    const float* m1  = (const float*)d_in[3];
    const float* m2  = (const float*)d_in[4];
    const float* fm1 = (const float*)d_in[5];
    const float* fm2 = (const float*)d_in[6];
    const float* W1  = (const float*)d_in[7];
    const float* b1  = (const float*)d_in[8];
    const float* W2  = (const float*)d_in[9];
    const float* b2  = (const float*)d_in[10];

    int E = in_sizes[2];
    int F = in_sizes[5];
    int N = in_sizes[0] / F;

    k_detect<<<1, 256>>>((const unsigned int*)ei, (long long)2 * E);
    k_init<<<(N + 255) / 256, 256>>>(N);
    k_deg<<<(E + 255) / 256, 256>>>(ei, w, m1, m2, E);
    k_rsqrt<<<(3 * N + 255) / 256, 256>>>(N);

    int NB = (N + 511) / 512;
    k_scan1<<<NB, 512>>>(N);
    k_scan2<<<1, 1024>>>(NB);
    k_scan3<<<(N + 511) / 512, 512>>>(N, E);
    k_scatter<<<(E + 255) / 256, 256>>>(ei, w, m1, m2, E);

    k_wcat<<<(FDIM * C3 + 255) / 256, 256>>>(W1, fm1, fm2);
    k_gemm<<<(N + 127) / 128, 256>>>(x, N);

    long long tot = (long long)N * C3;
    k_agg<<<(int)(((long long)N * 32 + 255) / 256), 256>>>(N);
    k_post1<<<(int)((tot + 255) / 256), 256>>>(b1, N);
    k_h2<<<(int)((tot + 255) / 256), 256>>>(W2, N);
    k_agg<<<(int)(((long long)N * 32 + 255) / 256), 256>>>(N);
    k_post2<<<(int)((tot + 255) / 256), 256>>>(b2, (float*)d_out, N);
}